// round 1
// baseline (speedup 1.0000x reference)
#include <cuda_runtime.h>
#include <math.h>

#define Bn   4
#define CIN  256
#define CE   64
#define Gn   4
#define Hn   80
#define Wn   80
#define Nn   (Hn*Wn)        // 6400
#define ROW  260            // G * 65
#define EPSV 1e-8f

// ---------------- static device scratch (no allocations allowed) ----------------
__device__ float g_ft   [Bn*Nn*CIN];   // feature transposed (b, n, c)
__device__ float g_embt [Bn*Nn*CE];    // embed transposed (b, n, o)
__device__ float g_gembt[Bn*Nn*CE];    // guide embed transposed
__device__ float g_conf [Bn*Nn*Gn];    // sigmoid conf (b, n, g)
__device__ float g_w    [Bn*Gn*Nn];    // edge weight in BFS-node order (b, g, k)
__device__ float g_scan [Bn*Nn*ROW];   // scan result rows (b, k, 260)
__device__ int   g_inv  [Bn*Nn];       // inverse of order
__device__ int   g_ls   [Bn*(Nn+2)];   // level start offsets
__device__ int   g_nlvl [Bn];

// ---------------- packed f32x2 FMA ----------------
__device__ __forceinline__ void ffma2(unsigned long long &d,
                                      unsigned long long a,
                                      unsigned long long b) {
    asm("fma.rn.f32x2 %0, %1, %2, %0;" : "+l"(d) : "l"(a), "l"(b));
}

// ---------------- K0: transpose feature (b,c,n) -> (b,n,c) ----------------
__global__ void k_transpose(const float* __restrict__ f) {
    __shared__ float t[32][33];
    int b = blockIdx.z, c0 = blockIdx.y * 32, n0 = blockIdx.x * 32;
    int tx = threadIdx.x, ty = threadIdx.y;         // 32 x 8
    const float* src = f + ((size_t)b * CIN + c0) * Nn + n0;
#pragma unroll
    for (int r = 0; r < 32; r += 8)
        t[ty + r][tx] = src[(size_t)(ty + r) * Nn + tx];
    __syncthreads();
    float* dst = g_ft + ((size_t)b * Nn + n0) * CIN + c0;
#pragma unroll
    for (int r = 0; r < 32; r += 8)
        dst[(size_t)(ty + r) * CIN + tx] = t[tx][ty + r];
}

// ---------------- K1: levels (pointer doubling) + inverse permutation ----------------
__global__ __launch_bounds__(256) void k_levels(const int* __restrict__ order,
                                                const int* __restrict__ parent) {
    extern __shared__ int sh[];
    int* a0 = sh;            // anc buf A
    int* a1 = sh + Nn;       // anc buf B
    int* l0 = sh + 2 * Nn;   // lvl buf A
    int* l1 = sh + 3 * Nn;   // lvl buf B
    int b = blockIdx.x, tid = threadIdx.x;
    const int* pp = parent + b * Nn;
    const int* od = order + b * Nn;
    for (int k = tid; k < Nn; k += blockDim.x) {
        a0[k] = pp[k];
        l0[k] = (k == 0) ? 0 : 1;
        g_inv[b * Nn + od[k]] = k;
    }
    __syncthreads();
    int* aa = a0; int* ab = a1; int* la = l0; int* lb = l1;
    for (int it = 0; it < 13; ++it) {         // 2^13 = 8192 >= max depth
        for (int k = tid; k < Nn; k += blockDim.x) {
            int a = aa[k];
            lb[k] = la[k] + la[a];
            ab[k] = aa[a];
        }
        __syncthreads();
        int* tmp = aa; aa = ab; ab = tmp;
        tmp = la; la = lb; lb = tmp;
    }
    // la[k] = depth of node at BFS position k (monotone nondecreasing)
    int* ls = g_ls + b * (Nn + 2);
    for (int k = tid; k < Nn; k += blockDim.x) {
        if (k == 0) ls[0] = 0;
        else if (la[k] != la[k - 1]) ls[la[k]] = k;
        if (k == Nn - 1) { g_nlvl[b] = la[k] + 1; ls[la[k] + 1] = Nn; }
    }
}

// ---------------- K2: skinny GEMMs via packed f32x2 FMA ----------------
// path 0: feature -> 64 embed + 4 conf(sigmoid);  path 1: guide -> 64 guide_embed
__global__ __launch_bounds__(256) void k_gemm(const float* __restrict__ feat,
                                              const float* __restrict__ guide,
                                              const float* __restrict__ We,
                                              const float* __restrict__ Wc,
                                              const float* __restrict__ Wg) {
    __shared__ char smraw[34816];
    float*  xs = reinterpret_cast<float*>(smraw);             // [32][128]
    float2* ws = reinterpret_cast<float2*>(smraw + 16384);    // [72][32] duplicated pairs
    float*  stage = reinterpret_cast<float*>(smraw);          // [128][68] (reuse)

    int tid = threadIdx.x;
    int os = tid >> 5;       // 0..7  (o slice of 9)
    int nq = tid & 31;       // 0..31 (n quad)
    int n0 = blockIdx.x * 128;
    int b  = blockIdx.y;
    int path = blockIdx.z;

    const float* X = (path == 0 ? feat : guide) + (size_t)b * CIN * Nn;

    unsigned long long acc[9][2];
#pragma unroll
    for (int j = 0; j < 9; ++j) { acc[j][0] = 0ull; acc[j][1] = 0ull; }

    for (int kc = 0; kc < 256; kc += 32) {
        // load X tile [32 k][128 n]
        const float* Xb = X + (size_t)kc * Nn + n0;
#pragma unroll
        for (int i = tid; i < 1024; i += 256) {
            int kk = i >> 5, c4 = i & 31;
            *reinterpret_cast<float4*>(&xs[kk * 128 + c4 * 4]) =
                *reinterpret_cast<const float4*>(&Xb[(size_t)kk * Nn + c4 * 4]);
        }
        // load W tile (duplicated pairs), zero-pad o>=68
#pragma unroll
        for (int i = tid; i < 2304; i += 256) {
            int o = i >> 5, kk = i & 31;
            float v = 0.f;
            if (path == 0) {
                if (o < 64)       v = We[o * 256 + kc + kk];
                else if (o < 68)  v = Wc[(o - 64) * 256 + kc + kk];
            } else {
                if (o < 64)       v = Wg[o * 256 + kc + kk];
            }
            ws[i] = make_float2(v, v);
        }
        __syncthreads();
#pragma unroll 2
        for (int kk = 0; kk < 32; ++kk) {
            float4 x4 = *reinterpret_cast<const float4*>(&xs[kk * 128 + nq * 4]);
            unsigned long long xlo = *reinterpret_cast<unsigned long long*>(&x4.x);
            unsigned long long xhi = *reinterpret_cast<unsigned long long*>(&x4.z);
#pragma unroll
            for (int j = 0; j < 9; ++j) {
                float2 wv = ws[(os * 9 + j) * 32 + kk];
                unsigned long long wp = *reinterpret_cast<unsigned long long*>(&wv);
                ffma2(acc[j][0], xlo, wp);
                ffma2(acc[j][1], xhi, wp);
            }
        }
        __syncthreads();
    }
    // stage results in smem [n][68]
#pragma unroll
    for (int j = 0; j < 9; ++j) {
        int o = os * 9 + j;
        if (o < 68) {
            float2 lo = *reinterpret_cast<float2*>(&acc[j][0]);
            float2 hi = *reinterpret_cast<float2*>(&acc[j][1]);
            stage[(nq * 4 + 0) * 68 + o] = lo.x;
            stage[(nq * 4 + 1) * 68 + o] = lo.y;
            stage[(nq * 4 + 2) * 68 + o] = hi.x;
            stage[(nq * 4 + 3) * 68 + o] = hi.y;
        }
    }
    __syncthreads();
    float* outt = (path == 0) ? g_embt : g_gembt;
#pragma unroll
    for (int i = tid; i < 2048; i += 256) {     // 128*64/4
        int n = i >> 4, c4 = i & 15;
        float4 v = *reinterpret_cast<float4*>(&stage[n * 68 + c4 * 4]);
        *reinterpret_cast<float4*>(&outt[((size_t)b * Nn + n0 + n) * 64 + c4 * 4]) = v;
    }
    if (path == 0) {
#pragma unroll
        for (int i = tid; i < 512; i += 256) {  // 128*4
            int n = i >> 2, gg = i & 3;
            float x = stage[n * 68 + 64 + gg];
            g_conf[((size_t)b * Nn + n0 + n) * 4 + gg] = 1.f / (1.f + expf(-x));
        }
    }
}

// ---------------- K3: edge weights w = exp(-(d_e + d_g + beta^2)) ----------------
__global__ __launch_bounds__(256) void k_w(const int* __restrict__ order,
                                           const int* __restrict__ parent,
                                           const float* __restrict__ beta) {
    int b = blockIdx.y;
    int k = blockIdx.x * 256 + threadIdx.x;
    if (k >= Nn) return;
    int n1 = order[b * Nn + k];
    int p  = parent[b * Nn + k];
    int n0 = order[b * Nn + p];
    const float4* e1 = reinterpret_cast<const float4*>(g_embt  + ((size_t)b * Nn + n1) * 64);
    const float4* e0 = reinterpret_cast<const float4*>(g_embt  + ((size_t)b * Nn + n0) * 64);
    const float4* q1 = reinterpret_cast<const float4*>(g_gembt + ((size_t)b * Nn + n1) * 64);
    const float4* q0 = reinterpret_cast<const float4*>(g_gembt + ((size_t)b * Nn + n0) * 64);
    float d[4] = {0.f, 0.f, 0.f, 0.f};
#pragma unroll
    for (int i = 0; i < 16; ++i) {
        float4 a = e1[i], c = e0[i];
        float dx = a.x - c.x, dy = a.y - c.y, dz = a.z - c.z, dw = a.w - c.w;
        d[i >> 2] += dx * dx + dy * dy + dz * dz + dw * dw;
    }
#pragma unroll
    for (int i = 0; i < 16; ++i) {
        float4 a = q1[i], c = q0[i];
        float dx = a.x - c.x, dy = a.y - c.y, dz = a.z - c.z, dw = a.w - c.w;
        d[i >> 2] += dx * dx + dy * dy + dz * dz + dw * dw;
    }
#pragma unroll
    for (int g = 0; g < 4; ++g) {
        float bb = beta[g];
        g_w[((size_t)b * 4 + g) * Nn + k] = expf(-(d[g] + bb * bb));
    }
}

// ---------------- K4: level-parallel tree filter scan (smem-resident) ----------------
// grid (9, 4, 4): chunk ci (8 chunks of 8 fg-channels + 1 chunk = norm), group g, batch b
__global__ __launch_bounds__(256, 1) void k_scan(const int* __restrict__ order,
                                                 const int* __restrict__ parent) {
    extern __shared__ float sm[];
    float* sagg = sm;            // [N][8]
    float* sw   = sm + Nn * 8;   // [N]
    int ci = blockIdx.x, g = blockIdx.y, b = blockIdx.z;
    int cn = (ci == 8) ? 1 : 8;
    int c0 = ci * 8;
    int tid = threadIdx.x;
    const int* pp = parent + b * Nn;
    const int* od = order + b * Nn;

    // load w slice
    const float* wsrc = g_w + ((size_t)b * 4 + g) * Nn;
    for (int k = tid; k < Nn; k += 256) sw[k] = wsrc[k];

    // init agg = gathered xs
    if (cn == 8) {
        for (int k = tid; k < Nn; k += 256) {
            int n = od[k];
            float cf = g_conf[((size_t)b * Nn + n) * 4 + g];
            const float4* f4 = reinterpret_cast<const float4*>(
                g_ft + ((size_t)b * Nn + n) * CIN + g * 64 + c0);
            float4 v0 = f4[0], v1 = f4[1];
            float* dst = &sagg[k * 8];
            dst[0] = v0.x * cf; dst[1] = v0.y * cf; dst[2] = v0.z * cf; dst[3] = v0.w * cf;
            dst[4] = v1.x * cf; dst[5] = v1.y * cf; dst[6] = v1.z * cf; dst[7] = v1.w * cf;
        }
    } else {
        for (int k = tid; k < Nn; k += 256) {
            int n = od[k];
            sagg[k * 8] = g_conf[((size_t)b * Nn + n) * 4 + g];   // norm channel
        }
    }
    __syncthreads();

    int nlvl = g_nlvl[b];
    const int* ls = g_ls + b * (Nn + 2);

    // ---- up-sweep: deepest level -> level 1 ----
    int e = Nn;
    for (int lev = nlvl - 1; lev >= 1; --lev) {
        int s = ls[lev];
        int cnt = e - s;
        if (cn == 8) {
            for (int i = tid; i < cnt * 8; i += 256) {
                int k = s + (i >> 3), c = i & 7;
                float wv = sw[k];
                atomicAdd(&sagg[pp[k] * 8 + c], wv * sagg[k * 8 + c]);
            }
        } else {
            for (int i = tid; i < cnt; i += 256) {
                int k = s + i;
                atomicAdd(&sagg[pp[k] * 8], sw[k] * sagg[k * 8]);
            }
        }
        e = s;
        __syncthreads();
    }

    // ---- down-sweep: level 1 -> deepest (in place) ----
    for (int lev = 1; lev < nlvl; ++lev) {
        int s = ls[lev], ee = ls[lev + 1];
        int cnt = ee - s;
        if (cn == 8) {
            for (int i = tid; i < cnt * 8; i += 256) {
                int k = s + (i >> 3), c = i & 7;
                float wv = sw[k];
                float a = sagg[k * 8 + c];
                float pv = sagg[pp[k] * 8 + c];
                sagg[k * 8 + c] = fmaf(wv, pv - wv * a, a);
            }
        } else {
            for (int i = tid; i < cnt; i += 256) {
                int k = s + i;
                float wv = sw[k];
                float a = sagg[k * 8];
                float pv = sagg[pp[k] * 8];
                sagg[k * 8] = fmaf(wv, pv - wv * a, a);
            }
        }
        __syncthreads();
    }

    // writeback
    if (cn == 8) {
        for (int k = tid; k < Nn; k += 256) {
            float* dst = g_scan + ((size_t)b * Nn + k) * ROW + g * 65 + c0;
#pragma unroll
            for (int c = 0; c < 8; ++c) dst[c] = sagg[k * 8 + c];
        }
    } else {
        for (int k = tid; k < Nn; k += 256)
            g_scan[((size_t)b * Nn + k) * ROW + g * 65 + 64] = sagg[k * 8];
    }
}

// ---------------- K5: normalize + un-permute + residual ----------------
__global__ __launch_bounds__(256) void k_final(const float* __restrict__ feat,
                                               const float* __restrict__ gammap,
                                               float* __restrict__ out) {
    __shared__ float tile[32 * 261];
    __shared__ int kq[32];
    int b = blockIdx.y, n0 = blockIdx.x * 32;
    int tid = threadIdx.x;
    if (tid < 32) kq[tid] = g_inv[b * Nn + n0 + tid];
    __syncthreads();
    for (int i = tid; i < 32 * 260; i += 256) {
        int r = i / 260, cc = i - r * 260;
        tile[r * 261 + cc] = g_scan[((size_t)b * Nn + kq[r]) * ROW + cc];
    }
    __syncthreads();
    float gamma = gammap[0];
    int nl = tid & 31;
    int cg = tid >> 5;
    for (int c = cg; c < 256; c += 8) {
        int gr = c >> 6, j = c & 63;
        float filt = tile[nl * 261 + gr * 65 + j];
        float norm = tile[nl * 261 + gr * 65 + 64];
        float res = filt / (EPSV + norm);
        size_t idx = ((size_t)b * CIN + c) * Nn + n0 + nl;
        out[idx] = fmaf(gamma, res, feat[idx]);
    }
}

// ---------------- launcher ----------------
extern "C" void kernel_launch(void* const* d_in, const int* in_sizes, int n_in,
                              void* d_out, int out_size) {
    const float* feature = (const float*)d_in[0];
    const float* guide   = (const float*)d_in[1];
    const float* We      = (const float*)d_in[2];
    const float* Wc      = (const float*)d_in[3];
    const float* Wg      = (const float*)d_in[4];
    const float* beta    = (const float*)d_in[5];
    const float* gamma   = (const float*)d_in[6];
    const int*   order   = (const int*)d_in[7];
    const int*   parent  = (const int*)d_in[8];
    float* out = (float*)d_out;

    cudaFuncSetAttribute(k_levels, cudaFuncAttributeMaxDynamicSharedMemorySize, 4 * Nn * 4);
    cudaFuncSetAttribute(k_scan,   cudaFuncAttributeMaxDynamicSharedMemorySize, Nn * 8 * 4 + Nn * 4);

    k_transpose<<<dim3(Nn / 32, CIN / 32, Bn), dim3(32, 8)>>>(feature);
    k_levels<<<Bn, 256, 4 * Nn * 4>>>(order, parent);
    k_gemm<<<dim3(Nn / 128, Bn, 2), 256>>>(feature, guide, We, Wc, Wg);
    k_w<<<dim3(Nn / 256, Bn), 256>>>(order, parent, beta);
    k_scan<<<dim3(9, Gn, Bn), 256, Nn * 8 * 4 + Nn * 4>>>(order, parent);
    k_final<<<dim3(Nn / 32, Bn), 256>>>(feature, gamma, out);
}

// round 2
// speedup vs baseline: 1.0611x; 1.0611x over previous
#include <cuda_runtime.h>
#include <math.h>

#define Bn   4
#define CIN  256
#define CE   64
#define Gn   4
#define Hn   80
#define Wn   80
#define Nn   (Hn*Wn)        // 6400
#define ROW  260            // G * 65
#define EPSV 1e-8f

// ---------------- static device scratch ----------------
__device__ float g_ft   [Bn*Nn*CIN];   // feature transposed (b, n, c)
__device__ float g_embt [Bn*Nn*CE];    // embed transposed (b, n, o)
__device__ float g_gembt[Bn*Nn*CE];    // guide embed transposed
__device__ float g_conf [Bn*Nn*Gn];    // sigmoid conf (b, n, g)
__device__ float g_w    [Bn*Gn*Nn];    // edge weight in BFS-node order (b, g, k)
__device__ float g_scan [Bn*Nn*ROW];   // scan result rows (b, k, 260)
__device__ int   g_inv  [Bn*Nn];       // inverse of order
__device__ int   g_ls   [Bn*(Nn+2)];   // level start offsets
__device__ int   g_nlvl [Bn];

// ---------------- packed f32x2 FMA ----------------
__device__ __forceinline__ void ffma2(unsigned long long &d,
                                      unsigned long long a,
                                      unsigned long long b) {
    asm("fma.rn.f32x2 %0, %1, %2, %0;" : "+l"(d) : "l"(a), "l"(b));
}

// ---------------- K0: transpose feature (b,c,n) -> (b,n,c) ----------------
__global__ void k_transpose(const float* __restrict__ f) {
    __shared__ float t[32][33];
    int b = blockIdx.z, c0 = blockIdx.y * 32, n0 = blockIdx.x * 32;
    int tx = threadIdx.x, ty = threadIdx.y;         // 32 x 8
    const float* src = f + ((size_t)b * CIN + c0) * Nn + n0;
#pragma unroll
    for (int r = 0; r < 32; r += 8)
        t[ty + r][tx] = src[(size_t)(ty + r) * Nn + tx];
    __syncthreads();
    float* dst = g_ft + ((size_t)b * Nn + n0) * CIN + c0;
#pragma unroll
    for (int r = 0; r < 32; r += 8)
        dst[(size_t)(ty + r) * CIN + tx] = t[tx][ty + r];
}

// ---------------- K1: levels (pointer doubling, early exit) + inverse perm ----------------
__global__ __launch_bounds__(256) void k_levels(const int* __restrict__ order,
                                                const int* __restrict__ parent) {
    extern __shared__ int sh[];
    int* a0 = sh;            // anc buf A
    int* a1 = sh + Nn;       // anc buf B
    int* l0 = sh + 2 * Nn;   // lvl buf A
    int* l1 = sh + 3 * Nn;   // lvl buf B
    __shared__ int s_more;
    int b = blockIdx.x, tid = threadIdx.x;
    const int* pp = parent + b * Nn;
    const int* od = order + b * Nn;
    for (int k = tid; k < Nn; k += blockDim.x) {
        a0[k] = pp[k];
        l0[k] = (k == 0) ? 0 : 1;
        g_inv[b * Nn + od[k]] = k;
    }
    __syncthreads();
    int* aa = a0; int* ab = a1; int* la = l0; int* lb = l1;
    for (int it = 0; it < 13; ++it) {
        if (tid == 0) s_more = 0;
        __syncthreads();
        int any = 0;
        for (int k = tid; k < Nn; k += blockDim.x) {
            int a = aa[k];
            lb[k] = la[k] + la[a];
            int na = aa[a];
            ab[k] = na;
            any |= na;
        }
        if (any) s_more = 1;
        __syncthreads();
        int* tmp = aa; aa = ab; ab = tmp;
        tmp = la; la = lb; lb = tmp;
        if (!s_more) break;
    }
    int* ls = g_ls + b * (Nn + 2);
    for (int k = tid; k < Nn; k += blockDim.x) {
        if (k == 0) ls[0] = 0;
        else if (la[k] != la[k - 1]) ls[la[k]] = k;
        if (k == Nn - 1) { g_nlvl[b] = la[k] + 1; ls[la[k] + 1] = Nn; }
    }
}

// ---------------- K2: skinny GEMMs via packed f32x2 FMA ----------------
__global__ __launch_bounds__(256) void k_gemm(const float* __restrict__ feat,
                                              const float* __restrict__ guide,
                                              const float* __restrict__ We,
                                              const float* __restrict__ Wc,
                                              const float* __restrict__ Wg) {
    __shared__ char smraw[34816];
    float*  xs = reinterpret_cast<float*>(smraw);             // [32][128]
    float2* ws = reinterpret_cast<float2*>(smraw + 16384);    // [72][32]
    float*  stage = reinterpret_cast<float*>(smraw);          // [128][68]

    int tid = threadIdx.x;
    int os = tid >> 5;
    int nq = tid & 31;
    int n0 = blockIdx.x * 128;
    int b  = blockIdx.y;
    int path = blockIdx.z;

    const float* X = (path == 0 ? feat : guide) + (size_t)b * CIN * Nn;

    unsigned long long acc[9][2];
#pragma unroll
    for (int j = 0; j < 9; ++j) { acc[j][0] = 0ull; acc[j][1] = 0ull; }

    for (int kc = 0; kc < 256; kc += 32) {
        const float* Xb = X + (size_t)kc * Nn + n0;
#pragma unroll
        for (int i = tid; i < 1024; i += 256) {
            int kk = i >> 5, c4 = i & 31;
            *reinterpret_cast<float4*>(&xs[kk * 128 + c4 * 4]) =
                *reinterpret_cast<const float4*>(&Xb[(size_t)kk * Nn + c4 * 4]);
        }
#pragma unroll
        for (int i = tid; i < 2304; i += 256) {
            int o = i >> 5, kk = i & 31;
            float v = 0.f;
            if (path == 0) {
                if (o < 64)       v = We[o * 256 + kc + kk];
                else if (o < 68)  v = Wc[(o - 64) * 256 + kc + kk];
            } else {
                if (o < 64)       v = Wg[o * 256 + kc + kk];
            }
            ws[i] = make_float2(v, v);
        }
        __syncthreads();
#pragma unroll 2
        for (int kk = 0; kk < 32; ++kk) {
            float4 x4 = *reinterpret_cast<const float4*>(&xs[kk * 128 + nq * 4]);
            unsigned long long xlo = *reinterpret_cast<unsigned long long*>(&x4.x);
            unsigned long long xhi = *reinterpret_cast<unsigned long long*>(&x4.z);
#pragma unroll
            for (int j = 0; j < 9; ++j) {
                float2 wv = ws[(os * 9 + j) * 32 + kk];
                unsigned long long wp = *reinterpret_cast<unsigned long long*>(&wv);
                ffma2(acc[j][0], xlo, wp);
                ffma2(acc[j][1], xhi, wp);
            }
        }
        __syncthreads();
    }
#pragma unroll
    for (int j = 0; j < 9; ++j) {
        int o = os * 9 + j;
        if (o < 68) {
            float2 lo = *reinterpret_cast<float2*>(&acc[j][0]);
            float2 hi = *reinterpret_cast<float2*>(&acc[j][1]);
            stage[(nq * 4 + 0) * 68 + o] = lo.x;
            stage[(nq * 4 + 1) * 68 + o] = lo.y;
            stage[(nq * 4 + 2) * 68 + o] = hi.x;
            stage[(nq * 4 + 3) * 68 + o] = hi.y;
        }
    }
    __syncthreads();
    float* outt = (path == 0) ? g_embt : g_gembt;
#pragma unroll
    for (int i = tid; i < 2048; i += 256) {
        int n = i >> 4, c4 = i & 15;
        float4 v = *reinterpret_cast<float4*>(&stage[n * 68 + c4 * 4]);
        *reinterpret_cast<float4*>(&outt[((size_t)b * Nn + n0 + n) * 64 + c4 * 4]) = v;
    }
    if (path == 0) {
#pragma unroll
        for (int i = tid; i < 512; i += 256) {
            int n = i >> 2, gg = i & 3;
            float x = stage[n * 68 + 64 + gg];
            g_conf[((size_t)b * Nn + n0 + n) * 4 + gg] = 1.f / (1.f + expf(-x));
        }
    }
}

// ---------------- K3: edge weights, 2 threads per node (one per channel half) ----------------
__global__ __launch_bounds__(256) void k_w(const int* __restrict__ order,
                                           const int* __restrict__ parent,
                                           const float* __restrict__ beta) {
    int b = blockIdx.y;
    int idx = blockIdx.x * 256 + threadIdx.x;
    int k = idx >> 1, half = idx & 1;
    if (k >= Nn) return;
    int n1 = order[b * Nn + k];
    int p  = parent[b * Nn + k];
    int n0 = order[b * Nn + p];
    int coff = half * 32;                           // groups {2*half, 2*half+1}
    const float4* e1 = reinterpret_cast<const float4*>(g_embt  + ((size_t)b * Nn + n1) * 64 + coff);
    const float4* e0 = reinterpret_cast<const float4*>(g_embt  + ((size_t)b * Nn + n0) * 64 + coff);
    const float4* q1 = reinterpret_cast<const float4*>(g_gembt + ((size_t)b * Nn + n1) * 64 + coff);
    const float4* q0 = reinterpret_cast<const float4*>(g_gembt + ((size_t)b * Nn + n0) * 64 + coff);
    float d[2] = {0.f, 0.f};
#pragma unroll
    for (int i = 0; i < 8; ++i) {
        float4 a = e1[i], c = e0[i];
        float dx = a.x - c.x, dy = a.y - c.y, dz = a.z - c.z, dw = a.w - c.w;
        d[i >> 2] += dx * dx + dy * dy + dz * dz + dw * dw;
    }
#pragma unroll
    for (int i = 0; i < 8; ++i) {
        float4 a = q1[i], c = q0[i];
        float dx = a.x - c.x, dy = a.y - c.y, dz = a.z - c.z, dw = a.w - c.w;
        d[i >> 2] += dx * dx + dy * dy + dz * dz + dw * dw;
    }
#pragma unroll
    for (int j = 0; j < 2; ++j) {
        int g = half * 2 + j;
        float bb = beta[g];
        g_w[((size_t)b * 4 + g) * Nn + k] = expf(-(d[j] + bb * bb));
    }
}

// ---------------- K4: level-parallel tree filter (smem agg, ls in smem, w/parent prefetched) ----------------
// CH=8: fg channel chunks; CH=1: norm channel
template<int CH>
__global__ __launch_bounds__(256, 1) void k_scan(const int* __restrict__ order,
                                                 const int* __restrict__ parent) {
    extern __shared__ float sagg[];          // [Nn*CH]
    __shared__ int sls[Nn + 2];
    __shared__ int s_nlvl;
    int ci = blockIdx.x, g = blockIdx.y, b = blockIdx.z;
    int c0 = ci * 8;
    int tid = threadIdx.x;
    const int* pp = parent + b * Nn;
    const int* od = order + b * Nn;
    const float* gw = g_w + ((size_t)b * 4 + g) * Nn;

    if (tid == 0) s_nlvl = g_nlvl[b];
    __syncthreads();
    int nlvl = s_nlvl;
    const int* gls = g_ls + b * (Nn + 2);
    for (int i = tid; i <= nlvl; i += 256) sls[i] = gls[i];

    // init agg
    if (CH == 8) {
        for (int k = tid; k < Nn; k += 256) {
            int n = od[k];
            float cf = g_conf[((size_t)b * Nn + n) * 4 + g];
            const float4* f4 = reinterpret_cast<const float4*>(
                g_ft + ((size_t)b * Nn + n) * CIN + g * 64 + c0);
            float4 v0 = f4[0], v1 = f4[1];
            float* dst = &sagg[k * 8];
            dst[0] = v0.x * cf; dst[1] = v0.y * cf; dst[2] = v0.z * cf; dst[3] = v0.w * cf;
            dst[4] = v1.x * cf; dst[5] = v1.y * cf; dst[6] = v1.z * cf; dst[7] = v1.w * cf;
        }
    } else {
        for (int k = tid; k < Nn; k += 256) {
            int n = od[k];
            sagg[k] = g_conf[((size_t)b * Nn + n) * 4 + g];
        }
    }
    __syncthreads();

    float rw[4]; int rp[4];

    // ---- up-sweep ----
    {
        int lev = nlvl - 1;
        int e = Nn;
        int s = sls[lev];
        int cnt = (e - s) * CH;
#pragma unroll
        for (int j = 0; j < 4; ++j) {
            int i = tid + 256 * j;
            if (i < cnt) { int k = s + i / CH; rp[j] = pp[k]; rw[j] = gw[k]; }
        }
        while (lev >= 1) {
            int s_c = s, e_c = e;
            float wc[4]; int pc[4];
#pragma unroll
            for (int j = 0; j < 4; ++j) { wc[j] = rw[j]; pc[j] = rp[j]; }
            int lev_n = lev - 1;
            int s_n = 0;
            if (lev_n >= 1) {
                s_n = sls[lev_n];
                int cntn = (s_c - s_n) * CH;
#pragma unroll
                for (int j = 0; j < 4; ++j) {
                    int i = tid + 256 * j;
                    if (i < cntn) { int k = s_n + i / CH; rp[j] = pp[k]; rw[j] = gw[k]; }
                }
            }
            int cntc = (e_c - s_c) * CH;
            int j = 0;
            for (int i = tid; i < cntc; i += 256, ++j) {
                int k = s_c + i / CH, c = i % CH;
                float wv; int p;
                if (j < 4) { wv = wc[j]; p = pc[j]; }
                else       { p = pp[k]; wv = gw[k]; }
                atomicAdd(&sagg[p * CH + c], wv * sagg[k * CH + c]);
            }
            __syncthreads();
            e = s_c; s = s_n; lev = lev_n;
        }
    }

    // ---- down-sweep ----
    if (nlvl > 1) {
        int lev = 1;
        int s = sls[1];
        int e = sls[2];
        int cnt = (e - s) * CH;
#pragma unroll
        for (int j = 0; j < 4; ++j) {
            int i = tid + 256 * j;
            if (i < cnt) { int k = s + i / CH; rp[j] = pp[k]; rw[j] = gw[k]; }
        }
        while (lev < nlvl) {
            int s_c = s, e_c = e;
            float wc[4]; int pc[4];
#pragma unroll
            for (int j = 0; j < 4; ++j) { wc[j] = rw[j]; pc[j] = rp[j]; }
            int lev_n = lev + 1;
            int s_n = 0, e_n = 0;
            if (lev_n < nlvl) {
                s_n = sls[lev_n]; e_n = sls[lev_n + 1];
                int cntn = (e_n - s_n) * CH;
#pragma unroll
                for (int j = 0; j < 4; ++j) {
                    int i = tid + 256 * j;
                    if (i < cntn) { int k = s_n + i / CH; rp[j] = pp[k]; rw[j] = gw[k]; }
                }
            }
            int cntc = (e_c - s_c) * CH;
            int j = 0;
            for (int i = tid; i < cntc; i += 256, ++j) {
                int k = s_c + i / CH, c = i % CH;
                float wv; int p;
                if (j < 4) { wv = wc[j]; p = pc[j]; }
                else       { p = pp[k]; wv = gw[k]; }
                float a  = sagg[k * CH + c];
                float pv = sagg[p * CH + c];
                sagg[k * CH + c] = fmaf(wv, pv - wv * a, a);
            }
            __syncthreads();
            s = s_n; e = e_n; lev = lev_n;
        }
    }

    // writeback
    if (CH == 8) {
        for (int k = tid; k < Nn; k += 256) {
            float* dst = g_scan + ((size_t)b * Nn + k) * ROW + g * 65 + c0;
#pragma unroll
            for (int c = 0; c < 8; ++c) dst[c] = sagg[k * 8 + c];
        }
    } else {
        for (int k = tid; k < Nn; k += 256)
            g_scan[((size_t)b * Nn + k) * ROW + g * 65 + 64] = sagg[k];
    }
}

// ---------------- K5: normalize + un-permute + residual ----------------
__global__ __launch_bounds__(256) void k_final(const float* __restrict__ feat,
                                               const float* __restrict__ gammap,
                                               float* __restrict__ out) {
    __shared__ float tile[32 * 261];
    __shared__ int kq[32];
    int b = blockIdx.y, n0 = blockIdx.x * 32;
    int tid = threadIdx.x;
    if (tid < 32) kq[tid] = g_inv[b * Nn + n0 + tid];
    __syncthreads();
    for (int i = tid; i < 32 * 260; i += 256) {
        int r = i / 260, cc = i - r * 260;
        tile[r * 261 + cc] = g_scan[((size_t)b * Nn + kq[r]) * ROW + cc];
    }
    __syncthreads();
    float gamma = gammap[0];
    int nl = tid & 31;
    int cg = tid >> 5;
    for (int c = cg; c < 256; c += 8) {
        int gr = c >> 6, j = c & 63;
        float filt = tile[nl * 261 + gr * 65 + j];
        float norm = tile[nl * 261 + gr * 65 + 64];
        float res = filt / (EPSV + norm);
        size_t idx = ((size_t)b * CIN + c) * Nn + n0 + nl;
        out[idx] = fmaf(gamma, res, feat[idx]);
    }
}

// ---------------- launcher ----------------
extern "C" void kernel_launch(void* const* d_in, const int* in_sizes, int n_in,
                              void* d_out, int out_size) {
    const float* feature = (const float*)d_in[0];
    const float* guide   = (const float*)d_in[1];
    const float* We      = (const float*)d_in[2];
    const float* Wc      = (const float*)d_in[3];
    const float* Wg      = (const float*)d_in[4];
    const float* beta    = (const float*)d_in[5];
    const float* gamma   = (const float*)d_in[6];
    const int*   order   = (const int*)d_in[7];
    const int*   parent  = (const int*)d_in[8];
    float* out = (float*)d_out;

    cudaFuncSetAttribute(k_levels, cudaFuncAttributeMaxDynamicSharedMemorySize, 4 * Nn * 4);
    cudaFuncSetAttribute(k_scan<8>, cudaFuncAttributeMaxDynamicSharedMemorySize, Nn * 8 * 4);
    cudaFuncSetAttribute(k_scan<1>, cudaFuncAttributeMaxDynamicSharedMemorySize, Nn * 4);

    k_transpose<<<dim3(Nn / 32, CIN / 32, Bn), dim3(32, 8)>>>(feature);
    k_levels<<<Bn, 256, 4 * Nn * 4>>>(order, parent);
    k_gemm<<<dim3(Nn / 128, Bn, 2), 256>>>(feature, guide, We, Wc, Wg);
    k_w<<<dim3(Nn * 2 / 256, Bn), 256>>>(order, parent, beta);
    k_scan<8><<<dim3(8, Gn, Bn), 256, Nn * 8 * 4>>>(order, parent);
    k_scan<1><<<dim3(1, Gn, Bn), 256, Nn * 4>>>(order, parent);
    k_final<<<dim3(Nn / 32, Bn), 256>>>(feature, gamma, out);
}

// round 3
// speedup vs baseline: 1.4723x; 1.3875x over previous
#include <cuda_runtime.h>
#include <math.h>

#define Bn   4
#define CIN  256
#define CE   64
#define Gn   4
#define Hn   80
#define Wn   80
#define Nn   (Hn*Wn)        // 6400
#define ROW  260            // G * 65
#define EPSV 1e-8f

// ---------------- static device scratch ----------------
__device__ float g_ft   [Bn*Nn*CIN];   // feature transposed (b, n, c)
__device__ float g_embt [Bn*Nn*CE];    // embed transposed (b, n, o)
__device__ float g_gembt[Bn*Nn*CE];    // guide embed transposed
__device__ float g_conf [Bn*Nn*Gn];    // sigmoid conf (b, n, g)
__device__ float g_w    [Bn*Gn*Nn];    // edge weight in BFS-node order (b, g, k)
__device__ float g_cA   [Bn*Nn*ROW];   // c buffer A (b, k, 260)
__device__ float g_cB   [Bn*Nn*ROW];   // c buffer B / final out
__device__ float g_m0   [Bn*Nn*4];     // jump multiplier ping
__device__ float g_m1   [Bn*Nn*4];     // jump multiplier pong
__device__ int   g_anc0 [Bn*Nn];       // jump ancestor ping
__device__ int   g_anc1 [Bn*Nn];       // jump ancestor pong
__device__ int   g_inv  [Bn*Nn];       // inverse of order
__device__ int   g_ls   [Bn*(Nn+2)];   // level start offsets
__device__ int   g_nlvl [Bn];

// ---------------- packed f32x2 FMA ----------------
__device__ __forceinline__ void ffma2(unsigned long long &d,
                                      unsigned long long a,
                                      unsigned long long b) {
    asm("fma.rn.f32x2 %0, %1, %2, %0;" : "+l"(d) : "l"(a), "l"(b));
}

// ---------------- K0: transpose feature (b,c,n) -> (b,n,c) ----------------
__global__ void k_transpose(const float* __restrict__ f) {
    __shared__ float t[32][33];
    int b = blockIdx.z, c0 = blockIdx.y * 32, n0 = blockIdx.x * 32;
    int tx = threadIdx.x, ty = threadIdx.y;         // 32 x 8
    const float* src = f + ((size_t)b * CIN + c0) * Nn + n0;
#pragma unroll
    for (int r = 0; r < 32; r += 8)
        t[ty + r][tx] = src[(size_t)(ty + r) * Nn + tx];
    __syncthreads();
    float* dst = g_ft + ((size_t)b * Nn + n0) * CIN + c0;
#pragma unroll
    for (int r = 0; r < 32; r += 8)
        dst[(size_t)(ty + r) * CIN + tx] = t[tx][ty + r];
}

// ---------------- K1: levels (pointer doubling, early exit) + inverse perm ----------------
__global__ __launch_bounds__(256) void k_levels(const int* __restrict__ order,
                                                const int* __restrict__ parent) {
    extern __shared__ int sh[];
    int* a0 = sh;
    int* a1 = sh + Nn;
    int* l0 = sh + 2 * Nn;
    int* l1 = sh + 3 * Nn;
    __shared__ int s_more;
    int b = blockIdx.x, tid = threadIdx.x;
    const int* pp = parent + b * Nn;
    const int* od = order + b * Nn;
    for (int k = tid; k < Nn; k += blockDim.x) {
        a0[k] = pp[k];
        l0[k] = (k == 0) ? 0 : 1;
        g_inv[b * Nn + od[k]] = k;
    }
    __syncthreads();
    int* aa = a0; int* ab = a1; int* la = l0; int* lb = l1;
    for (int it = 0; it < 13; ++it) {
        if (tid == 0) s_more = 0;
        __syncthreads();
        int any = 0;
        for (int k = tid; k < Nn; k += blockDim.x) {
            int a = aa[k];
            lb[k] = la[k] + la[a];
            int na = aa[a];
            ab[k] = na;
            any |= na;
        }
        if (any) s_more = 1;
        __syncthreads();
        int* tmp = aa; aa = ab; ab = tmp;
        tmp = la; la = lb; lb = tmp;
        if (!s_more) break;
    }
    int* ls = g_ls + b * (Nn + 2);
    for (int k = tid; k < Nn; k += blockDim.x) {
        if (k == 0) ls[0] = 0;
        else if (la[k] != la[k - 1]) ls[la[k]] = k;
        if (k == Nn - 1) { g_nlvl[b] = la[k] + 1; ls[la[k] + 1] = Nn; }
    }
}

// ---------------- K2: skinny GEMMs via packed f32x2 FMA ----------------
__global__ __launch_bounds__(256) void k_gemm(const float* __restrict__ feat,
                                              const float* __restrict__ guide,
                                              const float* __restrict__ We,
                                              const float* __restrict__ Wc,
                                              const float* __restrict__ Wg) {
    __shared__ char smraw[34816];
    float*  xs = reinterpret_cast<float*>(smraw);             // [32][128]
    float2* ws = reinterpret_cast<float2*>(smraw + 16384);    // [72][32]
    float*  stage = reinterpret_cast<float*>(smraw);          // [128][68]

    int tid = threadIdx.x;
    int os = tid >> 5;
    int nq = tid & 31;
    int n0 = blockIdx.x * 128;
    int b  = blockIdx.y;
    int path = blockIdx.z;

    const float* X = (path == 0 ? feat : guide) + (size_t)b * CIN * Nn;

    unsigned long long acc[9][2];
#pragma unroll
    for (int j = 0; j < 9; ++j) { acc[j][0] = 0ull; acc[j][1] = 0ull; }

    for (int kc = 0; kc < 256; kc += 32) {
        const float* Xb = X + (size_t)kc * Nn + n0;
#pragma unroll
        for (int i = tid; i < 1024; i += 256) {
            int kk = i >> 5, c4 = i & 31;
            *reinterpret_cast<float4*>(&xs[kk * 128 + c4 * 4]) =
                *reinterpret_cast<const float4*>(&Xb[(size_t)kk * Nn + c4 * 4]);
        }
#pragma unroll
        for (int i = tid; i < 2304; i += 256) {
            int o = i >> 5, kk = i & 31;
            float v = 0.f;
            if (path == 0) {
                if (o < 64)       v = We[o * 256 + kc + kk];
                else if (o < 68)  v = Wc[(o - 64) * 256 + kc + kk];
            } else {
                if (o < 64)       v = Wg[o * 256 + kc + kk];
            }
            ws[i] = make_float2(v, v);
        }
        __syncthreads();
#pragma unroll 2
        for (int kk = 0; kk < 32; ++kk) {
            float4 x4 = *reinterpret_cast<const float4*>(&xs[kk * 128 + nq * 4]);
            unsigned long long xlo = *reinterpret_cast<unsigned long long*>(&x4.x);
            unsigned long long xhi = *reinterpret_cast<unsigned long long*>(&x4.z);
#pragma unroll
            for (int j = 0; j < 9; ++j) {
                float2 wv = ws[(os * 9 + j) * 32 + kk];
                unsigned long long wp = *reinterpret_cast<unsigned long long*>(&wv);
                ffma2(acc[j][0], xlo, wp);
                ffma2(acc[j][1], xhi, wp);
            }
        }
        __syncthreads();
    }
#pragma unroll
    for (int j = 0; j < 9; ++j) {
        int o = os * 9 + j;
        if (o < 68) {
            float2 lo = *reinterpret_cast<float2*>(&acc[j][0]);
            float2 hi = *reinterpret_cast<float2*>(&acc[j][1]);
            stage[(nq * 4 + 0) * 68 + o] = lo.x;
            stage[(nq * 4 + 1) * 68 + o] = lo.y;
            stage[(nq * 4 + 2) * 68 + o] = hi.x;
            stage[(nq * 4 + 3) * 68 + o] = hi.y;
        }
    }
    __syncthreads();
    float* outt = (path == 0) ? g_embt : g_gembt;
#pragma unroll
    for (int i = tid; i < 2048; i += 256) {
        int n = i >> 4, c4 = i & 15;
        float4 v = *reinterpret_cast<float4*>(&stage[n * 68 + c4 * 4]);
        *reinterpret_cast<float4*>(&outt[((size_t)b * Nn + n0 + n) * 64 + c4 * 4]) = v;
    }
    if (path == 0) {
#pragma unroll
        for (int i = tid; i < 512; i += 256) {
            int n = i >> 2, gg = i & 3;
            float x = stage[n * 68 + 64 + gg];
            g_conf[((size_t)b * Nn + n0 + n) * 4 + gg] = 1.f / (1.f + expf(-x));
        }
    }
}

// ---------------- K3: edge weights, 2 threads per node ----------------
__global__ __launch_bounds__(256) void k_w(const int* __restrict__ order,
                                           const int* __restrict__ parent,
                                           const float* __restrict__ beta) {
    int b = blockIdx.y;
    int idx = blockIdx.x * 256 + threadIdx.x;
    int k = idx >> 1, half = idx & 1;
    if (k >= Nn) return;
    int n1 = order[b * Nn + k];
    int p  = parent[b * Nn + k];
    int n0 = order[b * Nn + p];
    int coff = half * 32;
    const float4* e1 = reinterpret_cast<const float4*>(g_embt  + ((size_t)b * Nn + n1) * 64 + coff);
    const float4* e0 = reinterpret_cast<const float4*>(g_embt  + ((size_t)b * Nn + n0) * 64 + coff);
    const float4* q1 = reinterpret_cast<const float4*>(g_gembt + ((size_t)b * Nn + n1) * 64 + coff);
    const float4* q0 = reinterpret_cast<const float4*>(g_gembt + ((size_t)b * Nn + n0) * 64 + coff);
    float d[2] = {0.f, 0.f};
#pragma unroll
    for (int i = 0; i < 8; ++i) {
        float4 a = e1[i], c = e0[i];
        float dx = a.x - c.x, dy = a.y - c.y, dz = a.z - c.z, dw = a.w - c.w;
        d[i >> 2] += dx * dx + dy * dy + dz * dz + dw * dw;
    }
#pragma unroll
    for (int i = 0; i < 8; ++i) {
        float4 a = q1[i], c = q0[i];
        float dx = a.x - c.x, dy = a.y - c.y, dz = a.z - c.z, dw = a.w - c.w;
        d[i >> 2] += dx * dx + dy * dy + dz * dz + dw * dw;
    }
#pragma unroll
    for (int j = 0; j < 2; ++j) {
        int g = half * 2 + j;
        float bb = beta[g];
        g_w[((size_t)b * 4 + g) * Nn + k] = expf(-(d[j] + bb * bb));
    }
}

// ---------------- K4a: up-sweep (level scatter, prefetched), writes c=(1-w^2)*agg ----------------
template<int CH>
__device__ __forceinline__ void up_core(float* sagg, const int* __restrict__ pp,
                                        const float* __restrict__ gw,
                                        const int* sls, int nlvl, int tid) {
    float rw[4]; int rp[4];
    int lev = nlvl - 1;
    int e = Nn;
    int s = sls[lev];
    int cnt = (e - s) * CH;
#pragma unroll
    for (int j = 0; j < 4; ++j) {
        int i = tid + 256 * j;
        if (i < cnt) { int k = s + i / CH; rp[j] = pp[k]; rw[j] = gw[k]; }
    }
    while (lev >= 1) {
        int s_c = s, e_c = e;
        float wc[4]; int pc[4];
#pragma unroll
        for (int j = 0; j < 4; ++j) { wc[j] = rw[j]; pc[j] = rp[j]; }
        int lev_n = lev - 1;
        int s_n = 0;
        if (lev_n >= 1) {
            s_n = sls[lev_n];
            int cntn = (s_c - s_n) * CH;
#pragma unroll
            for (int j = 0; j < 4; ++j) {
                int i = tid + 256 * j;
                if (i < cntn) { int k = s_n + i / CH; rp[j] = pp[k]; rw[j] = gw[k]; }
            }
        }
        int cntc = (e_c - s_c) * CH;
        int j = 0;
        for (int i = tid; i < cntc; i += 256, ++j) {
            int k = s_c + i / CH, c = i % CH;
            float wv; int p;
            if (j < 4) { wv = wc[j]; p = pc[j]; }
            else       { p = pp[k]; wv = gw[k]; }
            atomicAdd(&sagg[p * CH + c], wv * sagg[k * CH + c]);
        }
        __syncthreads();
        e = s_c; s = s_n; lev = lev_n;
    }
}

__global__ __launch_bounds__(256, 1) void k_up(const int* __restrict__ order,
                                               const int* __restrict__ parent) {
    extern __shared__ float sagg[];
    __shared__ int sls[Nn + 2];
    __shared__ int s_nlvl;
    int ci = blockIdx.x, g = blockIdx.y, b = blockIdx.z;
    int c0 = ci * 8;
    int tid = threadIdx.x;
    const int* pp = parent + b * Nn;
    const int* od = order + b * Nn;
    const float* gw = g_w + ((size_t)b * 4 + g) * Nn;

    if (tid == 0) s_nlvl = g_nlvl[b];
    __syncthreads();
    int nlvl = s_nlvl;
    const int* gls = g_ls + b * (Nn + 2);
    for (int i = tid; i <= nlvl; i += 256) sls[i] = gls[i];

    if (ci < 8) {
        for (int k = tid; k < Nn; k += 256) {
            int n = od[k];
            float cf = g_conf[((size_t)b * Nn + n) * 4 + g];
            const float4* f4 = reinterpret_cast<const float4*>(
                g_ft + ((size_t)b * Nn + n) * CIN + g * 64 + c0);
            float4 v0 = f4[0], v1 = f4[1];
            float* dst = &sagg[k * 8];
            dst[0] = v0.x * cf; dst[1] = v0.y * cf; dst[2] = v0.z * cf; dst[3] = v0.w * cf;
            dst[4] = v1.x * cf; dst[5] = v1.y * cf; dst[6] = v1.z * cf; dst[7] = v1.w * cf;
        }
        __syncthreads();
        up_core<8>(sagg, pp, gw, sls, nlvl, tid);
        for (int k = tid; k < Nn; k += 256) {
            float w = (k == 0) ? 0.f : gw[k];
            float f = (k == 0) ? 1.f : (1.f - w * w);
            float* dst = g_cA + ((size_t)b * Nn + k) * ROW + g * 65 + c0;
#pragma unroll
            for (int c = 0; c < 8; ++c) dst[c] = f * sagg[k * 8 + c];
        }
    } else {
        for (int k = tid; k < Nn; k += 256) {
            int n = od[k];
            sagg[k] = g_conf[((size_t)b * Nn + n) * 4 + g];
        }
        __syncthreads();
        up_core<1>(sagg, pp, gw, sls, nlvl, tid);
        for (int k = tid; k < Nn; k += 256) {
            float w = (k == 0) ? 0.f : gw[k];
            float f = (k == 0) ? 1.f : (1.f - w * w);
            g_cA[((size_t)b * Nn + k) * ROW + g * 65 + 64] = f * sagg[k];
        }
    }
}

// ---------------- K4b: affine jump doubling (global, throughput) ----------------
// (c,m,anc) <- (c + m*c[anc], m*m[anc], anc[anc]).  FIRST reads m from g_w / anc from parent.
template<int FIRST>
__global__ __launch_bounds__(256) void k_double(const float* __restrict__ c_in,
                                                float* __restrict__ c_out,
                                                const float* __restrict__ m_in,
                                                float* __restrict__ m_out,
                                                const int* __restrict__ anc_in,
                                                int* __restrict__ anc_out,
                                                const int* __restrict__ parent) {
    int b = blockIdx.y;
    int k = blockIdx.x * 2 + (threadIdx.x >> 7);
    int t = threadIdx.x & 127;
    int anc = FIRST ? parent[b * Nn + k] : anc_in[b * Nn + k];
    const float* cs = c_in + ((size_t)b * Nn + k) * ROW;
    const float* ca = c_in + ((size_t)b * Nn + anc) * ROW;
    float* co = c_out + ((size_t)b * Nn + k) * ROW;
#pragma unroll
    for (int s = 0; s < 3; ++s) {
        int ch = t + 128 * s;
        if (ch < ROW) {
            int g = (ch >= 195) ? 3 : (ch >= 130) ? 2 : (ch >= 65) ? 1 : 0;
            float m;
            if (FIRST) m = (k == 0) ? 0.f : g_w[((size_t)b * 4 + g) * Nn + k];
            else       m = m_in[((size_t)b * Nn + k) * 4 + g];
            co[ch] = fmaf(m, ca[ch], cs[ch]);
        }
    }
    if (t < 4) {
        float ms, ma;
        if (FIRST) {
            ms = (k == 0) ? 0.f : g_w[((size_t)b * 4 + t) * Nn + k];
            ma = (anc == 0) ? 0.f : g_w[((size_t)b * 4 + t) * Nn + anc];
        } else {
            ms = m_in[((size_t)b * Nn + k) * 4 + t];
            ma = m_in[((size_t)b * Nn + anc) * 4 + t];
        }
        m_out[((size_t)b * Nn + k) * 4 + t] = ms * ma;
    }
    if (t == 4) {
        anc_out[b * Nn + k] = FIRST ? parent[b * Nn + anc] : anc_in[b * Nn + anc];
    }
}

// ---------------- K4c: strided down-sweep (16 levels per phase) ----------------
template<int CH>
__device__ __forceinline__ void down_core(float* sout, const float* __restrict__ cin,
                                          const float* __restrict__ mm,
                                          const int* __restrict__ aa,
                                          const int* sls16, int nph,
                                          int coloff, int g, int tid) {
    float rc[4], rm[4]; int ra[4];
    int s = sls16[0], e = sls16[1];
    {
        int cnt = (e - s) * CH;
#pragma unroll
        for (int j = 0; j < 4; ++j) {
            int i = tid + 256 * j;
            if (i < cnt) {
                int k = s + i / CH, c = i % CH;
                rc[j] = cin[(size_t)k * ROW + coloff + c];
                rm[j] = mm[(size_t)k * 4 + g];
                ra[j] = aa[k];
            }
        }
    }
    for (int t = 0; t < nph; ++t) {
        int s_c = s, e_c = e;
        float cc[4], cm[4]; int ca[4];
#pragma unroll
        for (int j = 0; j < 4; ++j) { cc[j] = rc[j]; cm[j] = rm[j]; ca[j] = ra[j]; }
        int s_n = 0, e_n = 0;
        if (t + 1 < nph) {
            s_n = sls16[t + 1]; e_n = sls16[t + 2];
            int cntn = (e_n - s_n) * CH;
#pragma unroll
            for (int j = 0; j < 4; ++j) {
                int i = tid + 256 * j;
                if (i < cntn) {
                    int k = s_n + i / CH, c = i % CH;
                    rc[j] = cin[(size_t)k * ROW + coloff + c];
                    rm[j] = mm[(size_t)k * 4 + g];
                    ra[j] = aa[k];
                }
            }
        }
        int cntc = (e_c - s_c) * CH;
        int j = 0;
        for (int i = tid; i < cntc; i += 256, ++j) {
            int k = s_c + i / CH, c = i % CH;
            float cv, mv; int av;
            if (j < 4) { cv = cc[j]; mv = cm[j]; av = ca[j]; }
            else {
                cv = cin[(size_t)k * ROW + coloff + c];
                mv = mm[(size_t)k * 4 + g];
                av = aa[k];
            }
            sout[k * CH + c] = (t == 0) ? cv : fmaf(mv, sout[av * CH + c], cv);
        }
        __syncthreads();
        s = s_n; e = e_n;
    }
}

__global__ __launch_bounds__(256, 1) void k_down() {
    extern __shared__ float sout[];
    __shared__ int sls16[404];
    __shared__ int s_nlvl;
    int ci = blockIdx.x, g = blockIdx.y, b = blockIdx.z;
    int c0 = ci * 8;
    int coloff = g * 65 + c0;
    int tid = threadIdx.x;
    if (tid == 0) s_nlvl = g_nlvl[b];
    __syncthreads();
    int nlvl = s_nlvl;
    int nph = (nlvl + 15) / 16;
    const int* gls = g_ls + b * (Nn + 2);
    for (int i = tid; i <= nph; i += 256) {
        int lev = 16 * i;
        sls16[i] = (lev == 0) ? 0 : ((lev >= nlvl) ? Nn : gls[lev]);
    }
    __syncthreads();
    const float* cin = g_cA + (size_t)b * Nn * ROW;
    const float* mm  = g_m1 + (size_t)b * Nn * 4;
    const int*   aa  = g_anc1 + (size_t)b * Nn;

    if (ci < 8) {
        down_core<8>(sout, cin, mm, aa, sls16, nph, coloff, g, tid);
        for (int k = tid; k < Nn; k += 256) {
            float* dst = g_cB + ((size_t)b * Nn + k) * ROW + coloff;
#pragma unroll
            for (int c = 0; c < 8; ++c) dst[c] = sout[k * 8 + c];
        }
    } else {
        down_core<1>(sout, cin, mm, aa, sls16, nph, coloff, g, tid);
        for (int k = tid; k < Nn; k += 256)
            g_cB[((size_t)b * Nn + k) * ROW + coloff] = sout[k];
    }
}

// ---------------- K5: normalize + un-permute + residual ----------------
__global__ __launch_bounds__(256) void k_final(const float* __restrict__ feat,
                                               const float* __restrict__ gammap,
                                               float* __restrict__ out) {
    __shared__ float tile[32 * 261];
    __shared__ int kq[32];
    int b = blockIdx.y, n0 = blockIdx.x * 32;
    int tid = threadIdx.x;
    if (tid < 32) kq[tid] = g_inv[b * Nn + n0 + tid];
    __syncthreads();
    for (int i = tid; i < 32 * 260; i += 256) {
        int r = i / 260, cc = i - r * 260;
        tile[r * 261 + cc] = g_cB[((size_t)b * Nn + kq[r]) * ROW + cc];
    }
    __syncthreads();
    float gamma = gammap[0];
    int nl = tid & 31;
    int cg = tid >> 5;
    for (int c = cg; c < 256; c += 8) {
        int gr = c >> 6, j = c & 63;
        float filt = tile[nl * 261 + gr * 65 + j];
        float norm = tile[nl * 261 + gr * 65 + 64];
        float res = filt / (EPSV + norm);
        size_t idx = ((size_t)b * CIN + c) * Nn + n0 + nl;
        out[idx] = fmaf(gamma, res, feat[idx]);
    }
}

// ---------------- launcher ----------------
extern "C" void kernel_launch(void* const* d_in, const int* in_sizes, int n_in,
                              void* d_out, int out_size) {
    const float* feature = (const float*)d_in[0];
    const float* guide   = (const float*)d_in[1];
    const float* We      = (const float*)d_in[2];
    const float* Wc      = (const float*)d_in[3];
    const float* Wg      = (const float*)d_in[4];
    const float* beta    = (const float*)d_in[5];
    const float* gamma   = (const float*)d_in[6];
    const int*   order   = (const int*)d_in[7];
    const int*   parent  = (const int*)d_in[8];
    float* out = (float*)d_out;

    cudaFuncSetAttribute(k_levels, cudaFuncAttributeMaxDynamicSharedMemorySize, 4 * Nn * 4);
    cudaFuncSetAttribute(k_up,     cudaFuncAttributeMaxDynamicSharedMemorySize, Nn * 8 * 4);
    cudaFuncSetAttribute(k_down,   cudaFuncAttributeMaxDynamicSharedMemorySize, Nn * 8 * 4);

    float* cA = nullptr; float* cB = nullptr;
    float* m0 = nullptr; float* m1 = nullptr;
    int* a0 = nullptr; int* a1 = nullptr;
    cudaGetSymbolAddress((void**)&cA, g_cA);
    cudaGetSymbolAddress((void**)&cB, g_cB);
    cudaGetSymbolAddress((void**)&m0, g_m0);
    cudaGetSymbolAddress((void**)&m1, g_m1);
    cudaGetSymbolAddress((void**)&a0, g_anc0);
    cudaGetSymbolAddress((void**)&a1, g_anc1);

    k_transpose<<<dim3(Nn / 32, CIN / 32, Bn), dim3(32, 8)>>>(feature);
    k_levels<<<Bn, 256, 4 * Nn * 4>>>(order, parent);
    k_gemm<<<dim3(Nn / 128, Bn, 2), 256>>>(feature, guide, We, Wc, Wg);
    k_w<<<dim3(Nn * 2 / 256, Bn), 256>>>(order, parent, beta);
    k_up<<<dim3(9, Gn, Bn), 256, Nn * 8 * 4>>>(order, parent);
    // 4 doubling iterations: 1 -> 2 -> 4 -> 8 -> 16 step jumps
    k_double<1><<<dim3(Nn / 2, Bn), 256>>>(cA, cB, nullptr, m0, nullptr, a0, parent);
    k_double<0><<<dim3(Nn / 2, Bn), 256>>>(cB, cA, m0, m1, a0, a1, parent);
    k_double<0><<<dim3(Nn / 2, Bn), 256>>>(cA, cB, m1, m0, a1, a0, parent);
    k_double<0><<<dim3(Nn / 2, Bn), 256>>>(cB, cA, m0, m1, a0, a1, parent);
    k_down<<<dim3(9, Gn, Bn), 256, Nn * 8 * 4>>>();
    k_final<<<dim3(Nn / 32, Bn), 256>>>(feature, gamma, out);
}